// round 1
// baseline (speedup 1.0000x reference)
#include <cuda_runtime.h>
#include <math.h>

#define HW    65536
#define CF    384
#define EE    256
#define GG    512
#define NCC   16

// ---- scratch layout (floats) ----
#define S_CS   0            // cellsums  [512][384]
#define S_AF   196608       // allfv     [512][768]
#define S_GL   589824       // glob      [4][384]
#define S_AR   591360       // area      [512]
#define S_EM   591872       // emb       [512][256]
#define S_EP   722944       // embp      [4][256]
#define S_CP   723968       // comp      [4][16]
#define S_HH   724032       // hidden    [3][512][256]
#define S_RW   1117248      // rw        [3][512][64]
#define S_KF   1215552      // kf        [3][512][256]
#define S_VF   1608768      // vf        [3][512][256]
#define S_OB   2001984      // ob        [3][4][256]
#define S_OW   2005056      // obwo      [3][4][512]
#define SCRATCH_FLOATS 2011200

__device__ float g_scratch[SCRATCH_FLOATS];

// ---- d_out layout (floats) ----
#define O_OCT  0            // out_cell_type [512][16]
#define O_OE0  8192         // out_exprs[0]  [512][512]
#define O_OE1  270336
#define O_OE2  532480
#define O_OCTE 794624       // out_cell_type_expr [512][16]
#define O_GH   802816       // genes_h [512][256]
#define O_CMP  933888       // comp [4][16]
#define O_ARE  933952       // area [512]

// ============================================================
// Segment sum: one block per (channel c, batch b) plane.
// ============================================================
__global__ void segsum_kernel(const float* __restrict__ hd1, const float* __restrict__ h1,
                              const int* __restrict__ mask,
                              float* __restrict__ cellsums, float* __restrict__ glob)
{
    int c = blockIdx.x, b = blockIdx.y, tid = threadIdx.x;
    const float* plane = (c < 256) ? hd1 + ((size_t)(b * 256 + c) << 16)
                                   : h1  + ((size_t)(b * 128 + (c - 256)) << 16);
    const int* mp = mask + ((size_t)b << 16);

    __shared__ float acc[129];
    __shared__ float red[256];
    if (tid < 129) acc[tid] = 0.f;
    __syncthreads();

    float tot = 0.f;
    const float4* p4 = (const float4*)plane;
    const int4*   m4 = (const int4*)mp;
    for (int i = tid; i < HW / 4; i += 256) {
        float4 v = p4[i];
        int4  id = m4[i];
        tot += (v.x + v.y) + (v.z + v.w);
        if (id.x) atomicAdd(&acc[id.x], v.x);
        if (id.y) atomicAdd(&acc[id.y], v.y);
        if (id.z) atomicAdd(&acc[id.z], v.z);
        if (id.w) atomicAdd(&acc[id.w], v.w);
    }
    red[tid] = tot;
    __syncthreads();
    for (int s = 128; s > 0; s >>= 1) {
        if (tid < s) red[tid] += red[tid + s];
        __syncthreads();
    }
    if (tid == 0) glob[b * CF + c] = red[0] * (1.f / HW);
    for (int i = tid; i < 128; i += 256)
        cellsums[(size_t)(b * 128 + i) * CF + c] = acc[i + 1];
}

// ============================================================
// Area histogram: one block per batch.
// ============================================================
__global__ void area_kernel(const int* __restrict__ mask,
                            float* __restrict__ g_area, float* __restrict__ out_area)
{
    int b = blockIdx.x, tid = threadIdx.x;
    __shared__ int cnt[129];
    if (tid < 129) cnt[tid] = 0;
    __syncthreads();
    const int4* m4 = (const int4*)(mask + ((size_t)b << 16));
    for (int i = tid; i < HW / 4; i += 256) {
        int4 id = m4[i];
        if (id.x) atomicAdd(&cnt[id.x], 1);
        if (id.y) atomicAdd(&cnt[id.y], 1);
        if (id.z) atomicAdd(&cnt[id.z], 1);
        if (id.w) atomicAdd(&cnt[id.w], 1);
    }
    __syncthreads();
    for (int i = tid; i < 128; i += 256) {
        float a = (float)cnt[i + 1];
        g_area[b * 128 + i] = a;
        out_area[b * 128 + i] = a;
    }
}

// ============================================================
// Build all_fv = [cell_sums/area , glob(b)]   [512][768]
// ============================================================
__global__ void finalize_allfv(const float* __restrict__ cellsums,
                               const float* __restrict__ g_area,
                               const float* __restrict__ glob,
                               float* __restrict__ allfv)
{
    int n = blockIdx.x, tid = threadIdx.x;
    int b = n >> 7;
    float inva = 1.f / fmaxf(g_area[n], 1.f);
    for (int j = tid; j < 768; j += 256) {
        float v = (j < CF) ? cellsums[(size_t)n * CF + j] * inva
                           : glob[b * CF + (j - CF)];
        allfv[(size_t)n * 768 + j] = v;
    }
}

// ============================================================
// Generic batched fp32 GEMM:  C = op(A @ B), 32x32 tiles.
// ============================================================
__global__ void gemm_kernel(const float* __restrict__ A, int lda, long long sAz,
                            const float* __restrict__ B, int ldb, long long sBz,
                            float* __restrict__ C, int ldc, long long sCz,
                            int M, int N, int K, int relu)
{
    int z = blockIdx.z;
    A += (size_t)z * sAz; B += (size_t)z * sBz; C += (size_t)z * sCz;

    __shared__ float As[32][33];
    __shared__ float Bs[32][33];
    int tid = threadIdx.x;
    int tx = tid & 15, ty = tid >> 4;
    int row0 = blockIdx.y * 32, col0 = blockIdx.x * 32;

    float a00 = 0.f, a01 = 0.f, a10 = 0.f, a11 = 0.f;

    for (int k0 = 0; k0 < K; k0 += 32) {
        for (int i = tid; i < 32 * 32; i += 256) {
            int m = i >> 5, kk = i & 31;
            int gr = row0 + m, gc = k0 + kk;
            As[m][kk] = (gr < M && gc < K) ? A[(size_t)gr * lda + gc] : 0.f;
        }
        for (int i = tid; i < 32 * 32; i += 256) {
            int kk = i >> 5, n = i & 31;
            int gr = k0 + kk, gc = col0 + n;
            Bs[kk][n] = (gr < K && gc < N) ? B[(size_t)gr * ldb + gc] : 0.f;
        }
        __syncthreads();
#pragma unroll
        for (int kk = 0; kk < 32; kk++) {
            float av0 = As[ty * 2 + 0][kk];
            float av1 = As[ty * 2 + 1][kk];
            float bv0 = Bs[kk][tx * 2 + 0];
            float bv1 = Bs[kk][tx * 2 + 1];
            a00 += av0 * bv0; a01 += av0 * bv1;
            a10 += av1 * bv0; a11 += av1 * bv1;
        }
        __syncthreads();
    }
    int r0 = row0 + ty * 2, c0 = col0 + tx * 2;
    if (relu) {
        a00 = fmaxf(a00, 0.f); a01 = fmaxf(a01, 0.f);
        a10 = fmaxf(a10, 0.f); a11 = fmaxf(a11, 0.f);
    }
    if (r0 < M) {
        if (c0     < N) C[(size_t)r0 * ldc + c0]     = a00;
        if (c0 + 1 < N) C[(size_t)r0 * ldc + c0 + 1] = a01;
    }
    if (r0 + 1 < M) {
        if (c0     < N) C[(size_t)(r0 + 1) * ldc + c0]     = a10;
        if (c0 + 1 < N) C[(size_t)(r0 + 1) * ldc + c0 + 1] = a11;
    }
}

// ============================================================
// emb_patches = mean over 128 cells  -> [4][256]
// ============================================================
__global__ void embp_kernel(const float* __restrict__ emb, float* __restrict__ embp)
{
    int b = blockIdx.x, e = threadIdx.x;
    float s = 0.f;
    for (int i = 0; i < 128; i++)
        s += emb[(size_t)(b * 128 + i) * EE + e];
    embp[b * EE + e] = s * (1.f / 128.f);
}

// ============================================================
// comp = softmax(relu(embp @ w1) @ w2)   one block per batch.
// ============================================================
__global__ void comp_fused(const float* __restrict__ embp,
                           const float* __restrict__ w1, const float* __restrict__ w2,
                           float* __restrict__ comp, float* __restrict__ comp_out)
{
    int b = blockIdx.x, tid = threadIdx.x;
    __shared__ float ep[EE];
    __shared__ float t1[EE];
    __shared__ float t2[NCC];
    ep[tid] = embp[b * EE + tid];
    __syncthreads();
    float s = 0.f;
    for (int c = 0; c < EE; c++)
        s += ep[c] * w1[(size_t)c * EE + tid];
    t1[tid] = fmaxf(s, 0.f);
    __syncthreads();
    if (tid < NCC) {
        float s2 = 0.f;
        for (int j = 0; j < EE; j++)
            s2 += t1[j] * w2[(size_t)j * NCC + tid];
        t2[tid] = s2;
    }
    __syncthreads();
    if (tid == 0) {
        float m = t2[0];
        for (int o = 1; o < NCC; o++) m = fmaxf(m, t2[o]);
        float tot = 0.f;
        float e[NCC];
        for (int o = 0; o < NCC; o++) { e[o] = expf(t2[o] - m); tot += e[o]; }
        float inv = 1.f / tot;
        for (int o = 0; o < NCC; o++) {
            comp[b * NCC + o] = e[o] * inv;
            comp_out[b * NCC + o] = e[o] * inv;
        }
    }
}

// ============================================================
// Row softmax for rw logits  [3*512 rows][64]
// ============================================================
__global__ void softmax64_kernel(float* __restrict__ x)
{
    int r = blockIdx.x, tid = threadIdx.x;
    float* row = x + (size_t)r * 64;
    float v = row[tid];
    __shared__ float sm[4];
    int lane = tid & 31, warp = tid >> 5;
    float m = v;
    for (int off = 16; off; off >>= 1) m = fmaxf(m, __shfl_xor_sync(0xffffffff, m, off));
    if (lane == 0) sm[warp] = m;
    __syncthreads();
    m = fmaxf(sm[0], sm[1]);
    float e = expf(v - m);
    float s = e;
    for (int off = 16; off; off >>= 1) s += __shfl_xor_sync(0xffffffff, s, off);
    if (lane == 0) sm[2 + warp] = s;
    __syncthreads();
    s = sm[2] + sm[3];
    row[tid] = e / s;
}

// ============================================================
// Attention: 4 distinct q rows. grid (4 batches, 8 heads, 3 branches)
// ============================================================
__global__ void attn_kernel(const float* __restrict__ comp,
                            const float* __restrict__ ca_wq,   // [3][16][256]
                            const float* __restrict__ kf,      // [3][512][256]
                            const float* __restrict__ vf,
                            float* __restrict__ ob)            // [3][4][256]
{
    int b = blockIdx.x, h = blockIdx.y, br = blockIdx.z;
    int tid = threadIdx.x, lane = tid & 31, warp = tid >> 5;
    const float* wq  = ca_wq + (size_t)br * 16 * EE;
    const float* kfp = kf + (size_t)br * 512 * EE;
    const float* vfp = vf + (size_t)br * 512 * EE;

    __shared__ float q[32];
    __shared__ float sc[512];
    __shared__ float r1[256];
    __shared__ float part[8][32];

    if (tid < 32) {
        float s = 0.f;
        for (int c = 0; c < NCC; c++)
            s += comp[b * NCC + c] * wq[(size_t)c * EE + h * 32 + tid];
        q[tid] = s * 0.17677669529663687f;   // / sqrt(32)
    }
    __syncthreads();

    // scores: warp w handles kn = w*64 .. w*64+63
    for (int kk = 0; kk < 64; kk++) {
        int kn = warp * 64 + kk;
        float p = q[lane] * kfp[(size_t)kn * EE + h * 32 + lane];
        for (int off = 16; off; off >>= 1) p += __shfl_down_sync(0xffffffff, p, off);
        if (lane == 0) sc[kn] = p;
    }
    __syncthreads();

    // softmax over 512
    float m = fmaxf(sc[tid], sc[tid + 256]);
    r1[tid] = m; __syncthreads();
    for (int s = 128; s > 0; s >>= 1) { if (tid < s) r1[tid] = fmaxf(r1[tid], r1[tid + s]); __syncthreads(); }
    float maxv = r1[0]; __syncthreads();
    float e0 = expf(sc[tid] - maxv), e1 = expf(sc[tid + 256] - maxv);
    sc[tid] = e0; sc[tid + 256] = e1;
    r1[tid] = e0 + e1; __syncthreads();
    for (int s = 128; s > 0; s >>= 1) { if (tid < s) r1[tid] += r1[tid + s]; __syncthreads(); }
    float invs = 1.f / r1[0];

    // o accumulation: lane = d, warp strides kn
    float a = 0.f;
    for (int kn = warp; kn < 512; kn += 8)
        a += sc[kn] * vfp[(size_t)kn * EE + h * 32 + lane];
    part[warp][lane] = a;
    __syncthreads();
    if (tid < 32) {
        float s = 0.f;
        for (int w = 0; w < 8; w++) s += part[w][tid];
        ob[((size_t)br * 4 + b) * EE + h * 32 + tid] = s * invs;
    }
}

// ============================================================
// obwo = ob @ wo   (4 rows x 512) per branch. grid (4,1,3), 512 thr
// ============================================================
__global__ void obwo_kernel(const float* __restrict__ ob, const float* __restrict__ ca_wo,
                            float* __restrict__ obwo)
{
    int b = blockIdx.x, br = blockIdx.z, tid = threadIdx.x;
    const float* wo = ca_wo + (size_t)br * EE * GG;
    __shared__ float obs[EE];
    if (tid < EE) obs[tid] = ob[((size_t)br * 4 + b) * EE + tid];
    __syncthreads();
    float s = 0.f;
    for (int c = 0; c < EE; c++)
        s += obs[c] * wo[(size_t)c * GG + tid];
    obwo[((size_t)br * 4 + b) * GG + tid] = s;
}

// ============================================================
// out_exprs = relu(refw + tile(obwo)); in-place on d_out. grid (512,1,3)
// ============================================================
__global__ void addrelu_kernel(float* __restrict__ oe_base, const float* __restrict__ obwo)
{
    int n = blockIdx.x, br = blockIdx.z, g = threadIdx.x;
    int b = n >> 7;
    float* oe = oe_base + (size_t)br * 262144;
    float v = oe[(size_t)n * GG + g] + obwo[((size_t)br * 4 + b) * GG + g];
    oe[(size_t)n * GG + g] = fmaxf(v, 0.f);
}

// ============================================================
static inline void launch_gemm(const float* A, int lda, long long sAz,
                               const float* B, int ldb, long long sBz,
                               float* C, int ldc, long long sCz,
                               int M, int N, int K, int relu, int bz)
{
    dim3 grid((N + 31) / 32, (M + 31) / 32, bz);
    gemm_kernel<<<grid, 256>>>(A, lda, sAz, B, ldb, sBz, C, ldc, sCz, M, N, K, relu);
}

extern "C" void kernel_launch(void* const* d_in, const int* in_sizes, int n_in,
                              void* d_out, int out_size)
{
    (void)in_sizes; (void)n_in; (void)out_size;
    const float* hd1      = (const float*)d_in[0];
    const float* h1       = (const float*)d_in[1];
    const float* ref_orig = (const float*)d_in[2];
    const float* embed_w  = (const float*)d_in[3];
    const float* comp_w1  = (const float*)d_in[4];
    const float* comp_w2  = (const float*)d_in[5];
    const float* hist_w1  = (const float*)d_in[6];
    const float* hist_w2  = (const float*)d_in[7];
    const float* genes_w1 = (const float*)d_in[8];
    const float* genes_w2 = (const float*)d_in[9];
    const float* wref_w1  = (const float*)d_in[10];
    const float* wref_w2  = (const float*)d_in[11];
    const float* ca_wq    = (const float*)d_in[12];
    const float* ca_wk    = (const float*)d_in[13];
    const float* ca_wv    = (const float*)d_in[14];
    const float* ca_wo    = (const float*)d_in[15];
    const int*   mask     = (const int*)d_in[16];
    float* out = (float*)d_out;

    float* sc = nullptr;
    cudaGetSymbolAddress((void**)&sc, g_scratch);

    // 1. segment sums + global mean
    segsum_kernel<<<dim3(CF, 4), 256>>>(hd1, h1, mask, sc + S_CS, sc + S_GL);
    // 2. area histogram
    area_kernel<<<4, 256>>>(mask, sc + S_AR, out + O_ARE);
    // 3. all_fv
    finalize_allfv<<<512, 256>>>(sc + S_CS, sc + S_AR, sc + S_GL, sc + S_AF);
    // 4. emb = all_fv @ embed_w  [512,256]
    launch_gemm(sc + S_AF, 768, 0, embed_w, EE, 0, sc + S_EM, EE, 0, 512, EE, 768, 0, 1);
    // 5. emb_patches
    embp_kernel<<<4, 256>>>(sc + S_EM, sc + S_EP);
    // 6. comp
    comp_fused<<<4, 256>>>(sc + S_EP, comp_w1, comp_w2, sc + S_CP, out + O_CMP);
    // 7-8. out_cell_type
    launch_gemm(sc + S_EM, EE, 0, hist_w1, EE, 0, sc + S_HH, EE, 0, 512, EE, EE, 1, 1);
    launch_gemm(sc + S_HH, EE, 0, hist_w2, NCC, 0, out + O_OCT, NCC, 0, 512, NCC, EE, 0, 1);
    // 9. branch hidden: relu(emb @ wref_w1[i])  batched z=3
    launch_gemm(sc + S_EM, EE, 0, wref_w1, EE, (long long)EE * EE,
                sc + S_HH, EE, (long long)512 * EE, 512, EE, EE, 1, 3);
    // 10. rw logits
    launch_gemm(sc + S_HH, EE, (long long)512 * EE, wref_w2, 64, (long long)EE * 64,
                sc + S_RW, 64, (long long)512 * 64, 512, 64, EE, 0, 3);
    // 11. softmax rows
    softmax64_kernel<<<3 * 512, 64>>>(sc + S_RW);
    // 12. refw = rw @ ref_orig -> d_out out_exprs slots (pre-relu)
    launch_gemm(sc + S_RW, 64, (long long)512 * 64, ref_orig, GG, 0,
                out + O_OE0, GG, 262144LL, 512, GG, 64, 0, 3);
    // 13-14. kf/vf = refw @ wk/wv
    launch_gemm(out + O_OE0, GG, 262144LL, ca_wk, EE, (long long)GG * EE,
                sc + S_KF, EE, (long long)512 * EE, 512, EE, GG, 0, 3);
    launch_gemm(out + O_OE0, GG, 262144LL, ca_wv, EE, (long long)GG * EE,
                sc + S_VF, EE, (long long)512 * EE, 512, EE, GG, 0, 3);
    // 15. attention (4 distinct q rows per branch)
    attn_kernel<<<dim3(4, 8, 3), 256>>>(sc + S_CP, ca_wq, sc + S_KF, sc + S_VF, sc + S_OB);
    // 16. obwo
    obwo_kernel<<<dim3(4, 1, 3), 512>>>(sc + S_OB, ca_wo, sc + S_OW);
    // 17. out_exprs = relu(refw + tile(obwo))
    addrelu_kernel<<<dim3(512, 1, 3), 512>>>(out + O_OE0, sc + S_OW);
    // 18-19. genes_h, out_cell_type_expr
    launch_gemm(out + O_OE0, GG, 0, genes_w1, EE, 0, out + O_GH, EE, 0, 512, EE, GG, 1, 1);
    launch_gemm(out + O_GH, EE, 0, genes_w2, NCC, 0, out + O_OCTE, NCC, 0, 512, NCC, EE, 0, 1);
}

// round 2
// speedup vs baseline: 1.3639x; 1.3639x over previous
#include <cuda_runtime.h>
#include <math.h>

#define HW    65536
#define CF    384
#define EE    256
#define GG    512
#define NCC   16

// ---- scratch layout (floats) ----
#define S_CS   0            // cellsums  [512][384]
#define S_AF   196608       // allfv     [512][768]
#define S_GL   589824       // glob      [4][384]
#define S_AR   591360       // area      [512]
#define S_EM   591872       // emb       [512][256]
#define S_EP   722944       // embp      [4][256]
#define S_CP   723968       // comp      [4][16]
#define S_HH   724032       // hidden    [3][512][256]
#define S_RW   1117248      // rw        [3][512][64]
#define S_KF   1215552      // kf        [3][512][256]
#define S_VF   1608768      // vf        [3][512][256]
#define S_OB   2001984      // ob        [3][4][256]
#define S_OW   2005056      // obwo      [3][4][512]
#define S_P    2011200      // split-K partial buffers (max 786432 floats)
#define SCRATCH_FLOATS (2011200 + 786432)

__device__ float g_scratch[SCRATCH_FLOATS];

// ---- d_out layout (floats) ----
#define O_OCT  0            // out_cell_type [512][16]
#define O_OE0  8192         // out_exprs[0]  [512][512]
#define O_OCTE 794624       // out_cell_type_expr [512][16]
#define O_GH   802816       // genes_h [512][256]
#define O_CMP  933888       // comp [4][16]
#define O_ARE  933952       // area [512]

// ============================================================
// Segment sum: one block per (channel c, batch b) plane.
// ============================================================
__global__ void segsum_kernel(const float* __restrict__ hd1, const float* __restrict__ h1,
                              const int* __restrict__ mask,
                              float* __restrict__ cellsums, float* __restrict__ glob)
{
    int c = blockIdx.x, b = blockIdx.y, tid = threadIdx.x;
    const float* plane = (c < 256) ? hd1 + ((size_t)(b * 256 + c) << 16)
                                   : h1  + ((size_t)(b * 128 + (c - 256)) << 16);
    const int* mp = mask + ((size_t)b << 16);

    __shared__ float acc[129];
    __shared__ float red[256];
    if (tid < 129) acc[tid] = 0.f;
    __syncthreads();

    float tot = 0.f;
    const float4* p4 = (const float4*)plane;
    const int4*   m4 = (const int4*)mp;
    for (int i = tid; i < HW / 4; i += 256) {
        float4 v = p4[i];
        int4  id = m4[i];
        tot += (v.x + v.y) + (v.z + v.w);
        if (id.x) atomicAdd(&acc[id.x], v.x);
        if (id.y) atomicAdd(&acc[id.y], v.y);
        if (id.z) atomicAdd(&acc[id.z], v.z);
        if (id.w) atomicAdd(&acc[id.w], v.w);
    }
    red[tid] = tot;
    __syncthreads();
    for (int s = 128; s > 0; s >>= 1) {
        if (tid < s) red[tid] += red[tid + s];
        __syncthreads();
    }
    if (tid == 0) glob[b * CF + c] = red[0] * (1.f / HW);
    for (int i = tid; i < 128; i += 256)
        cellsums[(size_t)(b * 128 + i) * CF + c] = acc[i + 1];
}

// ============================================================
__global__ void area_kernel(const int* __restrict__ mask,
                            float* __restrict__ g_area, float* __restrict__ out_area)
{
    int b = blockIdx.x, tid = threadIdx.x;
    __shared__ int cnt[129];
    if (tid < 129) cnt[tid] = 0;
    __syncthreads();
    const int4* m4 = (const int4*)(mask + ((size_t)b << 16));
    for (int i = tid; i < HW / 4; i += 256) {
        int4 id = m4[i];
        if (id.x) atomicAdd(&cnt[id.x], 1);
        if (id.y) atomicAdd(&cnt[id.y], 1);
        if (id.z) atomicAdd(&cnt[id.z], 1);
        if (id.w) atomicAdd(&cnt[id.w], 1);
    }
    __syncthreads();
    for (int i = tid; i < 128; i += 256) {
        float a = (float)cnt[i + 1];
        g_area[b * 128 + i] = a;
        out_area[b * 128 + i] = a;
    }
}

// ============================================================
__global__ void finalize_allfv(const float* __restrict__ cellsums,
                               const float* __restrict__ g_area,
                               const float* __restrict__ glob,
                               float* __restrict__ allfv)
{
    int n = blockIdx.x, tid = threadIdx.x;
    int b = n >> 7;
    float inva = 1.f / fmaxf(g_area[n], 1.f);
    for (int j = tid; j < 768; j += 256) {
        float v = (j < CF) ? cellsums[(size_t)n * CF + j] * inva
                           : glob[b * CF + (j - CF)];
        allfv[(size_t)n * 768 + j] = v;
    }
}

// ============================================================
// GEMM: 64x64 tile, BK=16, 4x4 microtile, 256 threads.
// Requires M%64==0, N%64==0, (K/KS)%16==0.
// z dim = nz * KS; br = z/KS, kc = z%KS.
// If KS==1: C += br*sCz (relu applied). Else: partial slice z at
// C + z*M*ldc (relu deferred to reduce).
// ============================================================
__global__ void gemm64(const float* __restrict__ A, int lda, long long sAz,
                       const float* __restrict__ B, int ldb, long long sBz,
                       float* __restrict__ C, int ldc, long long sCz,
                       int M, int N, int K, int KS, int relu)
{
    int KC = K / KS;
    int br = blockIdx.z / KS, kc = blockIdx.z - br * KS;
    A += (size_t)br * sAz + (size_t)kc * KC;
    B += (size_t)br * sBz + (size_t)kc * KC * ldb;
    if (KS == 1) C += (size_t)br * sCz;
    else         C += (size_t)blockIdx.z * ((size_t)M * ldc);

    __shared__ float As[16][64];   // transposed A panel: As[k][m]
    __shared__ float Bs[16][64];
    int tid = threadIdx.x;
    int tx = tid & 15, ty = tid >> 4;
    int row0 = blockIdx.y * 64, col0 = blockIdx.x * 64;

    int arow = tid >> 2, ak4 = (tid & 3) * 4;   // A: 64 rows x 4 float4-chunks
    int brow = tid >> 4, bc4 = (tid & 15) * 4;  // B: 16 rows x 16 float4-chunks

    const float* Ap = A + (size_t)(row0 + arow) * lda + ak4;
    const float* Bp = B + (size_t)brow * ldb + col0 + bc4;

    float acc[4][4] = {};
    for (int k0 = 0; k0 < KC; k0 += 16) {
        float4 av = *(const float4*)(Ap + k0);
        float4 bv = *(const float4*)(Bp + (size_t)k0 * ldb);
        As[ak4 + 0][arow] = av.x;
        As[ak4 + 1][arow] = av.y;
        As[ak4 + 2][arow] = av.z;
        As[ak4 + 3][arow] = av.w;
        *(float4*)&Bs[brow][bc4] = bv;
        __syncthreads();
#pragma unroll
        for (int k = 0; k < 16; k++) {
            float4 a = *(const float4*)&As[k][ty * 4];
            float4 b = *(const float4*)&Bs[k][tx * 4];
            acc[0][0] += a.x * b.x; acc[0][1] += a.x * b.y; acc[0][2] += a.x * b.z; acc[0][3] += a.x * b.w;
            acc[1][0] += a.y * b.x; acc[1][1] += a.y * b.y; acc[1][2] += a.y * b.z; acc[1][3] += a.y * b.w;
            acc[2][0] += a.z * b.x; acc[2][1] += a.z * b.y; acc[2][2] += a.z * b.z; acc[2][3] += a.z * b.w;
            acc[3][0] += a.w * b.x; acc[3][1] += a.w * b.y; acc[3][2] += a.w * b.z; acc[3][3] += a.w * b.w;
        }
        __syncthreads();
    }
#pragma unroll
    for (int i = 0; i < 4; i++) {
        float4 v = make_float4(acc[i][0], acc[i][1], acc[i][2], acc[i][3]);
        if (relu && KS == 1) {
            v.x = fmaxf(v.x, 0.f); v.y = fmaxf(v.y, 0.f);
            v.z = fmaxf(v.z, 0.f); v.w = fmaxf(v.w, 0.f);
        }
        *(float4*)&C[(size_t)(row0 + ty * 4 + i) * ldc + col0 + tx * 4] = v;
    }
}

// Split-K reduction: C[br*sCz + idx] = op(sum_s P[(br*KS+s)*slice + idx])
__global__ void reducek_kernel(const float* __restrict__ P, float* __restrict__ C,
                               long long sCz, long long slice, int KS, int relu)
{
    int brz = blockIdx.y;
    long long idx = (long long)blockIdx.x * 256 + threadIdx.x;
    const float* p = P + (size_t)brz * KS * slice + idx;
    float s = 0.f;
    for (int j = 0; j < KS; j++) s += p[(size_t)j * slice];
    if (relu) s = fmaxf(s, 0.f);
    C[(size_t)brz * sCz + idx] = s;
}

// ============================================================
// Skinny GEMM: C[M,16] = op(A[M,K] @ B[K,16]); A contiguous (lda==K).
// grid M/32, 256 threads: 32 rows x 8 col-pairs.
// ============================================================
__global__ void gemmN16(const float* __restrict__ A, const float* __restrict__ B,
                        float* __restrict__ C, int K, int relu)
{
    extern __shared__ float As[];   // [32][K]
    int tid = threadIdx.x;
    int row0 = blockIdx.x * 32;
    for (int i = tid; i < 32 * K; i += 256)
        As[i] = A[(size_t)row0 * K + i];
    __syncthreads();
    int r = tid >> 3, cg = tid & 7;
    int c0 = cg * 2;
    float s0 = 0.f, s1 = 0.f;
    const float* ar = As + r * K;
#pragma unroll 4
    for (int k = 0; k < K; k++) {
        float a = ar[k];
        s0 += a * B[k * 16 + c0];
        s1 += a * B[k * 16 + c0 + 1];
    }
    if (relu) { s0 = fmaxf(s0, 0.f); s1 = fmaxf(s1, 0.f); }
    C[(size_t)(row0 + r) * 16 + c0]     = s0;
    C[(size_t)(row0 + r) * 16 + c0 + 1] = s1;
}

// ============================================================
__global__ void embp_kernel(const float* __restrict__ emb, float* __restrict__ embp)
{
    int b = blockIdx.x, e = threadIdx.x;
    float s = 0.f;
    for (int i = 0; i < 128; i++)
        s += emb[(size_t)(b * 128 + i) * EE + e];
    embp[b * EE + e] = s * (1.f / 128.f);
}

// ============================================================
__global__ void comp_fused(const float* __restrict__ embp,
                           const float* __restrict__ w1, const float* __restrict__ w2,
                           float* __restrict__ comp, float* __restrict__ comp_out)
{
    int b = blockIdx.x, tid = threadIdx.x;
    __shared__ float ep[EE];
    __shared__ float t1[EE];
    __shared__ float t2[NCC];
    ep[tid] = embp[b * EE + tid];
    __syncthreads();
    float s = 0.f;
    for (int c = 0; c < EE; c++)
        s += ep[c] * w1[(size_t)c * EE + tid];
    t1[tid] = fmaxf(s, 0.f);
    __syncthreads();
    if (tid < NCC) {
        float s2 = 0.f;
        for (int j = 0; j < EE; j++)
            s2 += t1[j] * w2[(size_t)j * NCC + tid];
        t2[tid] = s2;
    }
    __syncthreads();
    if (tid == 0) {
        float m = t2[0];
        for (int o = 1; o < NCC; o++) m = fmaxf(m, t2[o]);
        float tot = 0.f;
        float e[NCC];
        for (int o = 0; o < NCC; o++) { e[o] = expf(t2[o] - m); tot += e[o]; }
        float inv = 1.f / tot;
        for (int o = 0; o < NCC; o++) {
            comp[b * NCC + o] = e[o] * inv;
            comp_out[b * NCC + o] = e[o] * inv;
        }
    }
}

// ============================================================
__global__ void softmax64_kernel(float* __restrict__ x)
{
    int r = blockIdx.x, tid = threadIdx.x;
    float* row = x + (size_t)r * 64;
    float v = row[tid];
    __shared__ float sm[4];
    int lane = tid & 31, warp = tid >> 5;
    float m = v;
    for (int off = 16; off; off >>= 1) m = fmaxf(m, __shfl_xor_sync(0xffffffff, m, off));
    if (lane == 0) sm[warp] = m;
    __syncthreads();
    m = fmaxf(sm[0], sm[1]);
    float e = expf(v - m);
    float s = e;
    for (int off = 16; off; off >>= 1) s += __shfl_xor_sync(0xffffffff, s, off);
    if (lane == 0) sm[2 + warp] = s;
    __syncthreads();
    s = sm[2] + sm[3];
    row[tid] = e / s;
}

// ============================================================
__global__ void attn_kernel(const float* __restrict__ comp,
                            const float* __restrict__ ca_wq,
                            const float* __restrict__ kf,
                            const float* __restrict__ vf,
                            float* __restrict__ ob)
{
    int b = blockIdx.x, h = blockIdx.y, br = blockIdx.z;
    int tid = threadIdx.x, lane = tid & 31, warp = tid >> 5;
    const float* wq  = ca_wq + (size_t)br * 16 * EE;
    const float* kfp = kf + (size_t)br * 512 * EE;
    const float* vfp = vf + (size_t)br * 512 * EE;

    __shared__ float q[32];
    __shared__ float sc[512];
    __shared__ float r1[256];
    __shared__ float part[8][32];

    if (tid < 32) {
        float s = 0.f;
        for (int c = 0; c < NCC; c++)
            s += comp[b * NCC + c] * wq[(size_t)c * EE + h * 32 + tid];
        q[tid] = s * 0.17677669529663687f;
    }
    __syncthreads();

    for (int kk = 0; kk < 64; kk++) {
        int kn = warp * 64 + kk;
        float p = q[lane] * kfp[(size_t)kn * EE + h * 32 + lane];
        for (int off = 16; off; off >>= 1) p += __shfl_down_sync(0xffffffff, p, off);
        if (lane == 0) sc[kn] = p;
    }
    __syncthreads();

    float m = fmaxf(sc[tid], sc[tid + 256]);
    r1[tid] = m; __syncthreads();
    for (int s = 128; s > 0; s >>= 1) { if (tid < s) r1[tid] = fmaxf(r1[tid], r1[tid + s]); __syncthreads(); }
    float maxv = r1[0]; __syncthreads();
    float e0 = expf(sc[tid] - maxv), e1 = expf(sc[tid + 256] - maxv);
    sc[tid] = e0; sc[tid + 256] = e1;
    r1[tid] = e0 + e1; __syncthreads();
    for (int s = 128; s > 0; s >>= 1) { if (tid < s) r1[tid] += r1[tid + s]; __syncthreads(); }
    float invs = 1.f / r1[0];

    float a = 0.f;
    for (int kn = warp; kn < 512; kn += 8)
        a += sc[kn] * vfp[(size_t)kn * EE + h * 32 + lane];
    part[warp][lane] = a;
    __syncthreads();
    if (tid < 32) {
        float s = 0.f;
        for (int w = 0; w < 8; w++) s += part[w][tid];
        ob[((size_t)br * 4 + b) * EE + h * 32 + tid] = s * invs;
    }
}

// ============================================================
__global__ void obwo_kernel(const float* __restrict__ ob, const float* __restrict__ ca_wo,
                            float* __restrict__ obwo)
{
    int b = blockIdx.x, br = blockIdx.z, tid = threadIdx.x;
    const float* wo = ca_wo + (size_t)br * EE * GG;
    __shared__ float obs[EE];
    if (tid < EE) obs[tid] = ob[((size_t)br * 4 + b) * EE + tid];
    __syncthreads();
    float s = 0.f;
    for (int c = 0; c < EE; c++)
        s += obs[c] * wo[(size_t)c * GG + tid];
    obwo[((size_t)br * 4 + b) * GG + tid] = s;
}

// ============================================================
__global__ void addrelu_kernel(float* __restrict__ oe_base, const float* __restrict__ obwo)
{
    int n = blockIdx.x, br = blockIdx.z, g = threadIdx.x;
    int b = n >> 7;
    float* oe = oe_base + (size_t)br * 262144;
    float v = oe[(size_t)n * GG + g] + obwo[((size_t)br * 4 + b) * GG + g];
    oe[(size_t)n * GG + g] = fmaxf(v, 0.f);
}

// ============================================================
static inline void launch_gemm(const float* A, int lda, long long sAz,
                               const float* B, int ldb, long long sBz,
                               float* C, int ldc, long long sCz,
                               int M, int N, int K, int relu, int nz, int KS,
                               float* partial)
{
    dim3 grid(N / 64, M / 64, nz * KS);
    if (KS == 1) {
        gemm64<<<grid, 256>>>(A, lda, sAz, B, ldb, sBz, C, ldc, sCz, M, N, K, 1, relu);
    } else {
        gemm64<<<grid, 256>>>(A, lda, sAz, B, ldb, sBz, partial, ldc, 0, M, N, K, KS, 0);
        long long slice = (long long)M * ldc;
        reducek_kernel<<<dim3((unsigned)(slice / 256), nz), 256>>>(partial, C, sCz, slice, KS, relu);
    }
}

extern "C" void kernel_launch(void* const* d_in, const int* in_sizes, int n_in,
                              void* d_out, int out_size)
{
    (void)in_sizes; (void)n_in; (void)out_size;
    const float* hd1      = (const float*)d_in[0];
    const float* h1       = (const float*)d_in[1];
    const float* ref_orig = (const float*)d_in[2];
    const float* embed_w  = (const float*)d_in[3];
    const float* comp_w1  = (const float*)d_in[4];
    const float* comp_w2  = (const float*)d_in[5];
    const float* hist_w1  = (const float*)d_in[6];
    const float* hist_w2  = (const float*)d_in[7];
    const float* genes_w1 = (const float*)d_in[8];
    const float* genes_w2 = (const float*)d_in[9];
    const float* wref_w1  = (const float*)d_in[10];
    const float* wref_w2  = (const float*)d_in[11];
    const float* ca_wq    = (const float*)d_in[12];
    const float* ca_wk    = (const float*)d_in[13];
    const float* ca_wv    = (const float*)d_in[14];
    const float* ca_wo    = (const float*)d_in[15];
    const int*   mask     = (const int*)d_in[16];
    float* out = (float*)d_out;

    float* sc = nullptr;
    cudaGetSymbolAddress((void**)&sc, g_scratch);
    float* P = sc + S_P;

    // 1. segment sums + global mean
    segsum_kernel<<<dim3(CF, 4), 256>>>(hd1, h1, mask, sc + S_CS, sc + S_GL);
    // 2. area histogram
    area_kernel<<<4, 256>>>(mask, sc + S_AR, out + O_ARE);
    // 3. all_fv
    finalize_allfv<<<512, 256>>>(sc + S_CS, sc + S_AR, sc + S_GL, sc + S_AF);
    // 4. emb = all_fv @ embed_w  [512,256], K=768, split-K 4
    launch_gemm(sc + S_AF, 768, 0, embed_w, EE, 0, sc + S_EM, EE, 0,
                512, EE, 768, 0, 1, 4, P);
    // 5. emb_patches
    embp_kernel<<<4, 256>>>(sc + S_EM, sc + S_EP);
    // 6. comp
    comp_fused<<<4, 256>>>(sc + S_EP, comp_w1, comp_w2, sc + S_CP, out + O_CMP);
    // 7. hist hidden: relu(emb @ hist_w1), split-K 4
    launch_gemm(sc + S_EM, EE, 0, hist_w1, EE, 0, sc + S_HH, EE, 0,
                512, EE, EE, 1, 1, 4, P);
    // 8. out_cell_type = hidden @ hist_w2  [512,16]
    gemmN16<<<16, 256, 32 * EE * sizeof(float)>>>(sc + S_HH, hist_w2, out + O_OCT, EE, 0);
    // 9. branch hidden: relu(emb @ wref_w1[i]), z=3, split-K 2
    launch_gemm(sc + S_EM, EE, 0, wref_w1, EE, (long long)EE * EE,
                sc + S_HH, EE, (long long)512 * EE, 512, EE, EE, 1, 3, 2, P);
    // 10. rw logits: z=3, split-K 4
    launch_gemm(sc + S_HH, EE, (long long)512 * EE, wref_w2, 64, (long long)EE * 64,
                sc + S_RW, 64, (long long)512 * 64, 512, 64, EE, 0, 3, 4, P);
    // 11. softmax rows
    softmax64_kernel<<<3 * 512, 64>>>(sc + S_RW);
    // 12. refw = rw @ ref_orig -> out_exprs slots (pre-relu)
    launch_gemm(sc + S_RW, 64, (long long)512 * 64, ref_orig, GG, 0,
                out + O_OE0, GG, 262144LL, 512, GG, 64, 0, 3, 1, P);
    // 13-14. kf/vf = refw @ wk/wv, z=3, split-K 2
    launch_gemm(out + O_OE0, GG, 262144LL, ca_wk, EE, (long long)GG * EE,
                sc + S_KF, EE, (long long)512 * EE, 512, EE, GG, 0, 3, 2, P);
    launch_gemm(out + O_OE0, GG, 262144LL, ca_wv, EE, (long long)GG * EE,
                sc + S_VF, EE, (long long)512 * EE, 512, EE, GG, 0, 3, 2, P);
    // 15. attention
    attn_kernel<<<dim3(4, 8, 3), 256>>>(sc + S_CP, ca_wq, sc + S_KF, sc + S_VF, sc + S_OB);
    // 16. obwo
    obwo_kernel<<<dim3(4, 1, 3), 512>>>(sc + S_OB, ca_wo, sc + S_OW);
    // 17. out_exprs = relu(refw + tile(obwo))
    addrelu_kernel<<<dim3(512, 1, 3), 512>>>(out + O_OE0, sc + S_OW);
    // 18. genes_h = relu(out_exprs[0] @ genes_w1), split-K 4
    launch_gemm(out + O_OE0, GG, 0, genes_w1, EE, 0, out + O_GH, EE, 0,
                512, EE, GG, 1, 1, 4, P);
    // 19. out_cell_type_expr = genes_h @ genes_w2
    gemmN16<<<16, 256, 32 * EE * sizeof(float)>>>(out + O_GH, genes_w2, out + O_OCTE, EE, 0);
}